// round 5
// baseline (speedup 1.0000x reference)
#include <cuda_runtime.h>
#include <cstdint>

// Depth-of-field scatter-as-gather.
// out(q) = sum_t w*rgb / (sum_t w + eps)
// w ∝ mask(t) * sat(coc_s - dist_t + 0.5) * sigmoid(4*(disp_s - disp_q))
//
// R5 vs R4 (135 us; fma 59% / MUFU ~64% / issue 70%, occ 47%):
//  - tanh.approx.f16x2: ONE MUFU serves the two dests that share a tap
//    (d-pair packed f32->f16x2, tanh'd, widened back; w0/w/accum stay f32).
//  - __launch_bounds__(256,5): cap regs at 51 -> 5 CTAs/SM -> occ 62%.

#define H_ 1024
#define W_ 1024
#define RAD 5
#define TILE 32
#define SH 42               // TILE + 2*RAD
#define NTHREADS 256
#define V 4                 // dest pixels per thread (vertical)

__device__ __forceinline__ uint64_t pk2(float lo, float hi) {
    uint64_t d;
    asm("mov.b64 %0, {%1, %2};" : "=l"(d) : "f"(lo), "f"(hi));
    return d;
}
__device__ __forceinline__ void unpk2(uint64_t d, float& lo, float& hi) {
    asm("mov.b64 {%0, %1}, %2;" : "=f"(lo), "=f"(hi) : "l"(d));
}
__device__ __forceinline__ void fma2(uint64_t& acc, uint64_t a, uint64_t b) {
    asm("fma.rn.f32x2 %0, %1, %2, %3;" : "=l"(acc) : "l"(a), "l"(b), "l"(acc));
}
// Packed tanh: {th0, th1} = tanh(f16({d0, d1})), widened back to f32.
__device__ __forceinline__ void tanh2_fast(float d0, float d1, float& th0, float& th1) {
    asm("{\n\t"
        ".reg .b32 h, t;\n\t"
        ".reg .f16 lo, hi;\n\t"
        "cvt.rn.f16x2.f32 h, %3, %2;\n\t"   // first src -> high half
        "tanh.approx.f16x2 t, h;\n\t"
        "mov.b32 {lo, hi}, t;\n\t"
        "cvt.f32.f16 %0, lo;\n\t"
        "cvt.f32.f16 %1, hi;\n\t"
        "}"
        : "=f"(th0), "=f"(th1) : "f"(d0), "f"(d1));
}

__global__ __launch_bounds__(NTHREADS, 5) void dof_kernel(
    const float* __restrict__ xin,   // (4, 4, 1024, 1024): r,g,b,disp planes
    const float* __restrict__ le,    // (4,) lens effects
    float* __restrict__ out)         // (4, 3, 1024, 1024)
{
    __shared__ float4 sh[SH * SH];   // (r, g, b, 2*disp)

    const int b  = blockIdx.z;
    const float kh = 0.5f * fabsf(le[b]);   // coc = kh * |2*disp|
    const int tx = threadIdx.x;              // 0..31
    const int ty = threadIdx.y;              // 0..7
    const int tid = ty * 32 + tx;
    const int x0 = blockIdx.x * TILE - RAD;
    const int y0 = blockIdx.y * TILE - RAD;

    const float* pr = xin + (size_t)(b * 4 + 0) * (H_ * W_);
    const float* pg = xin + (size_t)(b * 4 + 1) * (H_ * W_);
    const float* pb = xin + (size_t)(b * 4 + 2) * (H_ * W_);
    const float* pd = xin + (size_t)(b * 4 + 3) * (H_ * W_);

    // Cooperative tile load with edge-clamp (matches jnp.pad mode='edge')
    for (int i = tid; i < SH * SH; i += NTHREADS) {
        int ly = i / SH;
        int lx = i - ly * SH;
        int gy = min(max(y0 + ly, 0), H_ - 1);
        int gx = min(max(x0 + lx, 0), W_ - 1);
        int gi = gy * W_ + gx;
        sh[i] = make_float4(pr[gi], pg[gi], pb[gi], 2.0f * pd[gi]);
    }
    __syncthreads();

    // CT[n] = sqrt(n) - 0.5, n = oy^2+ox^2 (compile-time folded)
    constexpr float CT[31] = {
        -0.5f,       0.5f,        0.91421356f, 0.f,         1.5f,
         1.73606798f, 0.f,        0.f,         2.32842712f, 2.5f,
         2.66227766f, 0.f,        0.f,         3.10555128f, 0.f,
         0.f,         3.5f,       3.62310563f, 3.74264069f, 0.f,
         3.97213595f, 0.f,        0.f,         0.f,         0.f,
         4.5f,        4.59901951f,0.f,         0.f,         4.88516481f,
         0.f };

    // This thread's 4 dest pixels: rows ty*V .. ty*V+3 of the tile
    const int syb = ty * V + RAD;             // shared row of dest k=0
    const int sxb = tx + RAD;
    const float4* dst0 = &sh[syb * SH + sxb];

    float eq[V];
    #pragma unroll
    for (int k = 0; k < V; k++) eq[k] = dst0[k * SH].w;   // 2*disp at dests

    uint64_t acc_rg[V], acc_bd[V];
    #pragma unroll
    for (int k = 0; k < V; k++) { acc_rg[k] = 0ull; acc_bd[k] = 0ull; }

    #pragma unroll
    for (int sr = -RAD; sr <= RAD + V - 1; sr++) {
        // min over k of (sr-k)^2 — compile-time
        const int d0s = sr * sr, d1s = (sr-1)*(sr-1), d2s = (sr-2)*(sr-2), d3s = (sr-3)*(sr-3);
        const int minsq = min(min(d0s, d1s), min(d2s, d3s));
        const float4* rowp = dst0 + sr * SH;

        #pragma unroll
        for (int ox = -RAD; ox <= RAD; ox++) {
            if (ox * ox + minsq > 30) continue;           // no dest uses this tap
            float4 s = rowp[ox];                          // one LDS.128, 4 dests
            float coc = kh * fabsf(s.w);
            uint64_t rg = pk2(s.x, s.y);
            uint64_t b1 = pk2(s.z, 1.0f);

            #pragma unroll
            for (int kp = 0; kp < V; kp += 2) {           // dest pairs share one tanh
                const int oy0 = sr - kp;
                const int oy1 = sr - (kp + 1);
                const int n0 = oy0 * oy0 + ox * ox;
                const int n1 = oy1 * oy1 + ox * ox;
                const bool v0 = (oy0 >= -RAD && oy0 <= RAD && n0 <= 30);
                const bool v1 = (oy1 >= -RAD && oy1 <= RAD && n1 <= 30);
                if (!v0 && !v1) continue;

                float dd0 = s.w - eq[kp];
                float dd1 = s.w - eq[kp + 1];
                float th0, th1;
                tanh2_fast(dd0, dd1, th0, th1);           // 1 MUFU for 2 dests

                if (v0) {
                    float w0 = __saturatef(coc - CT[n0]); // sat(coc - dist + 0.5)
                    float w  = fmaf(w0, th0, w0);         // = 2*w0*sigmoid(...)
                    uint64_t w2 = pk2(w, w);
                    fma2(acc_rg[kp], w2, rg);
                    fma2(acc_bd[kp], w2, b1);
                }
                if (v1) {
                    float w0 = __saturatef(coc - CT[n1]);
                    float w  = fmaf(w0, th1, w0);
                    uint64_t w2 = pk2(w, w);
                    fma2(acc_rg[kp + 1], w2, rg);
                    fma2(acc_bd[kp + 1], w2, b1);
                }
            }
        }
    }

    const int gx_out = blockIdx.x * TILE + tx;
    const int gy0    = blockIdx.y * TILE + ty * V;
    #pragma unroll
    for (int k = 0; k < V; k++) {
        float nr, ng, nb, dn;
        unpk2(acc_rg[k], nr, ng);
        unpk2(acc_bd[k], nb, dn);
        float inv = 1.0f / (dn + 2e-8f);                  // weights doubled -> 2*eps
        size_t o = ((size_t)(b * 3) * H_ + gy0 + k) * W_ + gx_out;
        out[o]               = nr * inv;
        out[o + H_ * W_]     = ng * inv;
        out[o + 2 * H_ * W_] = nb * inv;
    }
}

extern "C" void kernel_launch(void* const* d_in, const int* in_sizes, int n_in,
                              void* d_out, int out_size) {
    const float* x  = (const float*)d_in[0];   // (4,4,1024,1024) f32
    const float* le = (const float*)d_in[1];   // (4,1) f32
    // d_in[2] (diskernel) and d_in[3] (lens_mask) are pure functions of LENS=11,
    // baked in as compile-time constants.
    dim3 grid(W_ / TILE, H_ / TILE, 4);
    dim3 blk(32, 8);
    dof_kernel<<<grid, blk>>>(x, le, (float*)d_out);
}

// round 7
// speedup vs baseline: 1.1148x; 1.1148x over previous
#include <cuda_runtime.h>

// Depth-of-field scatter-as-gather.
// out(q) = sum_t w*rgb / (sum_t w + eps)
// w ∝ mask(t) * sat(coc_s - dist_t + 0.5) * sigmoid(4*(disp_s - disp_q))
//
// R7 == R6 resubmission (R6 hit the infra-level container failure, never ran).
//  - scalar f32 accumulation (4 FFMA; no u64 pairing, no pack movs)
//  - __launch_bounds__(256,5): 5 CTAs/SM (R5 showed 48 regs is achievable)
//  - V=4 vertical register reuse (one LDS.128 tap serves 4 dests)
//  - weight fold w = fma(w0, tanh, w0), eps 2e-8 (exact)

#define H_ 1024
#define W_ 1024
#define RAD 5
#define TILE 32
#define SH 42               // TILE + 2*RAD
#define NTHREADS 256
#define V 4                 // dest pixels per thread (vertical)

__device__ __forceinline__ float tanh_fast(float x) {
    float y;
    asm("tanh.approx.f32 %0, %1;" : "=f"(y) : "f"(x));
    return y;
}

__global__ __launch_bounds__(NTHREADS, 5) void dof_kernel(
    const float* __restrict__ xin,   // (4, 4, 1024, 1024): r,g,b,disp planes
    const float* __restrict__ le,    // (4,) lens effects
    float* __restrict__ out)         // (4, 3, 1024, 1024)
{
    __shared__ float4 sh[SH * SH];   // (r, g, b, 2*disp)

    const int b  = blockIdx.z;
    const float kh = 0.5f * fabsf(le[b]);   // coc = kh * |2*disp|
    const int tx = threadIdx.x;              // 0..31
    const int ty = threadIdx.y;              // 0..7
    const int tid = ty * 32 + tx;
    const int x0 = blockIdx.x * TILE - RAD;
    const int y0 = blockIdx.y * TILE - RAD;

    const float* pr = xin + (size_t)(b * 4 + 0) * (H_ * W_);
    const float* pg = xin + (size_t)(b * 4 + 1) * (H_ * W_);
    const float* pb = xin + (size_t)(b * 4 + 2) * (H_ * W_);
    const float* pd = xin + (size_t)(b * 4 + 3) * (H_ * W_);

    // Cooperative tile load with edge-clamp (matches jnp.pad mode='edge')
    for (int i = tid; i < SH * SH; i += NTHREADS) {
        int ly = i / SH;
        int lx = i - ly * SH;
        int gy = min(max(y0 + ly, 0), H_ - 1);
        int gx = min(max(x0 + lx, 0), W_ - 1);
        int gi = gy * W_ + gx;
        sh[i] = make_float4(pr[gi], pg[gi], pb[gi], 2.0f * pd[gi]);
    }
    __syncthreads();

    // CT[n] = sqrt(n) - 0.5, n = oy^2+ox^2 (compile-time folded)
    constexpr float CT[31] = {
        -0.5f,       0.5f,        0.91421356f, 0.f,         1.5f,
         1.73606798f, 0.f,        0.f,         2.32842712f, 2.5f,
         2.66227766f, 0.f,        0.f,         3.10555128f, 0.f,
         0.f,         3.5f,       3.62310563f, 3.74264069f, 0.f,
         3.97213595f, 0.f,        0.f,         0.f,         0.f,
         4.5f,        4.59901951f,0.f,         0.f,         4.88516481f,
         0.f };

    // This thread's 4 dest pixels: rows ty*V .. ty*V+3 of the tile
    const int syb = ty * V + RAD;             // shared row of dest k=0
    const int sxb = tx + RAD;
    const float4* dst0 = &sh[syb * SH + sxb];

    float eq[V];
    #pragma unroll
    for (int k = 0; k < V; k++) eq[k] = dst0[k * SH].w;   // 2*disp at dests

    float anr[V], ang[V], anb[V], adn[V];
    #pragma unroll
    for (int k = 0; k < V; k++) { anr[k] = 0.f; ang[k] = 0.f; anb[k] = 0.f; adn[k] = 0.f; }

    #pragma unroll
    for (int sr = -RAD; sr <= RAD + V - 1; sr++) {
        // min over k of (sr-k)^2 — compile-time
        const int d0s = sr * sr, d1s = (sr-1)*(sr-1), d2s = (sr-2)*(sr-2), d3s = (sr-3)*(sr-3);
        const int minsq = min(min(d0s, d1s), min(d2s, d3s));
        const float4* rowp = dst0 + sr * SH;

        #pragma unroll
        for (int ox = -RAD; ox <= RAD; ox++) {
            if (ox * ox + minsq > 30) continue;           // no dest uses this tap
            float4 s = rowp[ox];                          // one LDS.128, 4 dests
            float coc = kh * fabsf(s.w);                  // shared per tap

            #pragma unroll
            for (int k = 0; k < V; k++) {
                const int oy = sr - k;
                if (oy < -RAD || oy > RAD) continue;
                const int n = oy * oy + ox * ox;
                if (n > 30) continue;                     // disk mask
                float w0 = __saturatef(coc - CT[n]);      // FADD.SAT, imm
                float th = tanh_fast(s.w - eq[k]);        // tanh(2*(sd-sq))
                float w  = fmaf(w0, th, w0);              // = 2*w0*sigmoid(...)
                anr[k] = fmaf(w, s.x, anr[k]);
                ang[k] = fmaf(w, s.y, ang[k]);
                anb[k] = fmaf(w, s.z, anb[k]);
                adn[k] += w;
            }
        }
    }

    const int gx_out = blockIdx.x * TILE + tx;
    const int gy0    = blockIdx.y * TILE + ty * V;
    #pragma unroll
    for (int k = 0; k < V; k++) {
        float inv = 1.0f / (adn[k] + 2e-8f);              // weights doubled -> 2*eps
        size_t o = ((size_t)(b * 3) * H_ + gy0 + k) * W_ + gx_out;
        out[o]               = anr[k] * inv;
        out[o + H_ * W_]     = ang[k] * inv;
        out[o + 2 * H_ * W_] = anb[k] * inv;
    }
}

extern "C" void kernel_launch(void* const* d_in, const int* in_sizes, int n_in,
                              void* d_out, int out_size) {
    const float* x  = (const float*)d_in[0];   // (4,4,1024,1024) f32
    const float* le = (const float*)d_in[1];   // (4,1) f32
    // d_in[2] (diskernel) and d_in[3] (lens_mask) are pure functions of LENS=11,
    // baked in as compile-time constants.
    dim3 grid(W_ / TILE, H_ / TILE, 4);
    dim3 blk(32, 8);
    dof_kernel<<<grid, blk>>>(x, le, (float*)d_out);
}